// round 1
// baseline (speedup 1.0000x reference)
#include <cuda_runtime.h>
#include <cuda_bf16.h>

#define N_NODES 100000
#define N_EDGES 1600000
#define NFEAT   128
#define NHID    16
#define NCLS    40

// -------- scratch (device globals; no allocation allowed) --------
__device__ float g_p[N_NODES * 32];    // [:,0:16] = x@w_self1, [:,16:32] = x@w_neigh1
__device__ float g_h[N_NODES * 16];    // layer-1 output (post relu)
__device__ float g_m2[N_NODES * 16];   // mean of h over in-neighbors
__device__ int   g_deg[N_NODES];
__device__ int   g_rowptr[N_NODES + 1];
__device__ int   g_cursor[N_NODES];
__device__ int   g_eidx[N_EDGES];      // src ids sorted by dst (CSR)
__device__ int   g_bsum[256];
__device__ int   g_boff[256];

// -------- CSR construction --------
__global__ void k_zero_deg() {
    int i = blockIdx.x * blockDim.x + threadIdx.x;
    if (i < N_NODES) g_deg[i] = 0;
}

__global__ void k_count(const int* __restrict__ dst) {
    int e = blockIdx.x * blockDim.x + threadIdx.x;
    if (e < N_EDGES) atomicAdd(&g_deg[dst[e]], 1);
}

// block-level sums (196 blocks x 512)
__global__ void k_scanA() {
    __shared__ int s[512];
    int i = blockIdx.x * 512 + threadIdx.x;
    int v = (i < N_NODES) ? g_deg[i] : 0;
    s[threadIdx.x] = v;
    __syncthreads();
    for (int off = 256; off > 0; off >>= 1) {
        if (threadIdx.x < off) s[threadIdx.x] += s[threadIdx.x + off];
        __syncthreads();
    }
    if (threadIdx.x == 0) g_bsum[blockIdx.x] = s[0];
}

__global__ void k_scanB(int nb) {
    if (threadIdx.x == 0) {
        int run = 0;
        for (int i = 0; i < nb; i++) { g_boff[i] = run; run += g_bsum[i]; }
        g_rowptr[N_NODES] = run;   // == N_EDGES
    }
}

__global__ void k_scanC() {
    __shared__ int s[512];
    int tid = threadIdx.x;
    int i = blockIdx.x * 512 + tid;
    int v = (i < N_NODES) ? g_deg[i] : 0;
    s[tid] = v;
    __syncthreads();
    // Hillis-Steele inclusive scan
    for (int off = 1; off < 512; off <<= 1) {
        int t = (tid >= off) ? s[tid - off] : 0;
        __syncthreads();
        s[tid] += t;
        __syncthreads();
    }
    if (i < N_NODES) {
        int excl = s[tid] - v + g_boff[blockIdx.x];
        g_rowptr[i] = excl;
        g_cursor[i] = excl;
    }
}

__global__ void k_fill(const int* __restrict__ src, const int* __restrict__ dst) {
    int e = blockIdx.x * blockDim.x + threadIdx.x;
    if (e < N_EDGES) {
        int d = dst[e];
        int pos = atomicAdd(&g_cursor[d], 1);
        g_eidx[pos] = src[e];
    }
}

// -------- GEMM1: p = x @ [w_self1 | w_neigh1]   (100000 x 128) @ (128 x 32) --------
// block = 128 threads, tile 64 rows x 32 cols, per-thread 4x4
__global__ void __launch_bounds__(128) k_gemm1(const float* __restrict__ x,
                                               const float* __restrict__ wn1,
                                               const float* __restrict__ ws1) {
    __shared__ float xs[64 * 129];   // padded stride 129 (conflict-free)
    __shared__ float ws[128 * 32];
    int tid = threadIdx.x;
    int row0 = blockIdx.x * 64;

    // weights: cols 0..15 = w_self1, 16..31 = w_neigh1
    for (int i = tid; i < 128 * 32; i += 128) {
        int k = i >> 5, c = i & 31;
        ws[i] = (c < 16) ? ws1[k * 16 + c] : wn1[k * 16 + (c - 16)];
    }
    // x tile (coalesced)
    for (int i = tid; i < 64 * 128; i += 128) {
        int r = i >> 7, c = i & 127;
        int gr = row0 + r;
        xs[r * 129 + c] = (gr < N_NODES) ? x[gr * 128 + c] : 0.f;
    }
    __syncthreads();

    int cg = tid & 7;          // col group of 4
    int rg = tid >> 3;         // row group of 4 (0..15)
    float acc[4][4];
#pragma unroll
    for (int r = 0; r < 4; r++)
#pragma unroll
        for (int c = 0; c < 4; c++) acc[r][c] = 0.f;

    const float* wp = ws + cg * 4;
    const float* xp = xs + (rg * 4) * 129;
#pragma unroll 4
    for (int k = 0; k < 128; k++) {
        float4 wv = *(const float4*)(wp + k * 32);
#pragma unroll
        for (int r = 0; r < 4; r++) {
            float xv = xp[r * 129 + k];
            acc[r][0] += xv * wv.x;
            acc[r][1] += xv * wv.y;
            acc[r][2] += xv * wv.z;
            acc[r][3] += xv * wv.w;
        }
    }
#pragma unroll
    for (int r = 0; r < 4; r++) {
        int gr = row0 + rg * 4 + r;
        if (gr < N_NODES) {
            float4 o = make_float4(acc[r][0], acc[r][1], acc[r][2], acc[r][3]);
            *(float4*)(&g_p[gr * 32 + cg * 4]) = o;
        }
    }
}

// -------- layer-1 aggregate + combine + relu --------
// half-warp per node: lanes 0..15 -> node A, 16..31 -> node B; feat = lane & 15
__global__ void k_agg1(const float* __restrict__ b1) {
    int tid = threadIdx.x;
    int lane = tid & 31;
    int warp = tid >> 5;
    int n = blockIdx.x * 16 + warp * 2 + (lane >> 4);
    int f = lane & 15;
    if (n >= N_NODES) return;
    int beg = g_rowptr[n];
    int end = g_rowptr[n + 1];
    float acc = 0.f;
    for (int i = beg; i < end; i++) {
        int s = g_eidx[i];
        acc += g_p[s * 32 + 16 + f];   // projected-neighbor part
    }
    float deg = (float)(end - beg);
    float mean = acc / fmaxf(deg, 1.f);
    float v = g_p[n * 32 + f] + mean + b1[f];
    g_h[n * 16 + f] = fmaxf(v, 0.f);
}

// -------- layer-2 aggregate (mean of h over in-neighbors) --------
__global__ void k_agg2() {
    int tid = threadIdx.x;
    int lane = tid & 31;
    int warp = tid >> 5;
    int n = blockIdx.x * 16 + warp * 2 + (lane >> 4);
    int f = lane & 15;
    if (n >= N_NODES) return;
    int beg = g_rowptr[n];
    int end = g_rowptr[n + 1];
    float acc = 0.f;
    for (int i = beg; i < end; i++) {
        int s = g_eidx[i];
        acc += g_h[s * 16 + f];
    }
    float deg = (float)(end - beg);
    g_m2[n * 16 + f] = acc / fmaxf(deg, 1.f);
}

// -------- output: out = h @ w_self2 + m2 @ w_neigh2 + b2 --------
// block = 320 threads = 8 nodes x 40 classes
__global__ void __launch_bounds__(320) k_out(const float* __restrict__ wn2,
                                             const float* __restrict__ ws2,
                                             const float* __restrict__ b2,
                                             float* __restrict__ out) {
    __shared__ float sws[16 * 40];
    __shared__ float swn[16 * 40];
    __shared__ float sb[40];
    __shared__ float hr[8][16];
    __shared__ float mr[8][16];
    int tid = threadIdx.x;
    for (int i = tid; i < 640; i += 320) { sws[i] = ws2[i]; swn[i] = wn2[i]; }
    if (tid < 40) sb[tid] = b2[tid];
    int n0 = blockIdx.x * 8;
    if (tid < 128) {
        int nl = tid >> 4, f = tid & 15;
        int n = n0 + nl;
        hr[nl][f] = (n < N_NODES) ? g_h[n * 16 + f] : 0.f;
    } else if (tid < 256) {
        int t = tid - 128;
        int nl = t >> 4, f = t & 15;
        int n = n0 + nl;
        mr[nl][f] = (n < N_NODES) ? g_m2[n * 16 + f] : 0.f;
    }
    __syncthreads();
    int c = tid % 40;
    int nl = tid / 40;
    int n = n0 + nl;
    if (n < N_NODES) {
        float acc = sb[c];
#pragma unroll
        for (int k = 0; k < 16; k++)
            acc += hr[nl][k] * sws[k * 40 + c] + mr[nl][k] * swn[k * 40 + c];
        out[n * 40 + c] = acc;
    }
}

extern "C" void kernel_launch(void* const* d_in, const int* in_sizes, int n_in,
                              void* d_out, int out_size) {
    const float* x   = (const float*)d_in[0];
    const int*   src = (const int*)d_in[1];
    const int*   dst = (const int*)d_in[2];
    const float* wn1 = (const float*)d_in[3];
    const float* ws1 = (const float*)d_in[4];
    const float* b1  = (const float*)d_in[5];
    const float* wn2 = (const float*)d_in[6];
    const float* ws2 = (const float*)d_in[7];
    const float* b2  = (const float*)d_in[8];
    float* out = (float*)d_out;

    k_zero_deg<<<(N_NODES + 255) / 256, 256>>>();
    k_count<<<(N_EDGES + 255) / 256, 256>>>(dst);
    k_scanA<<<196, 512>>>();
    k_scanB<<<1, 32>>>(196);
    k_scanC<<<196, 512>>>();
    k_fill<<<(N_EDGES + 255) / 256, 256>>>(src, dst);
    k_gemm1<<<(N_NODES + 63) / 64, 128>>>(x, wn1, ws1);
    k_agg1<<<(N_NODES + 15) / 16, 256>>>(b1);
    k_agg2<<<(N_NODES + 15) / 16, 256>>>();
    k_out<<<(N_NODES + 7) / 8, 320>>>(wn2, ws2, b2, out);
}

// round 2
// speedup vs baseline: 1.0643x; 1.0643x over previous
#include <cuda_runtime.h>
#include <cuda_bf16.h>

#define N_NODES 100000
#define N_EDGES 1600000
#define NFEAT   128
#define NHID    16
#define NCLS    40

// -------- scratch (device globals) --------
__device__ float g_p[N_NODES * 32];    // [:,0:16] = x@w_self1, [:,16:32] = x@w_neigh1
__device__ float g_h[N_NODES * 16];    // layer-1 output (post relu)
__device__ float g_m2[N_NODES * 16];   // mean of h over in-neighbors
__device__ int   g_deg[N_NODES];
__device__ int   g_rowptr[N_NODES + 1];
__device__ int   g_cursor[N_NODES];
__device__ int   g_eidx[N_EDGES];      // src ids grouped by dst (CSR)
__device__ int   g_bsum[256];
__device__ int   g_boff[256];

// -------- CSR construction --------
__global__ void k_count(const int* __restrict__ dst) {
    int e = blockIdx.x * blockDim.x + threadIdx.x;
    if (e * 4 < N_EDGES) {
        int4 d = ((const int4*)dst)[e];
        atomicAdd(&g_deg[d.x], 1);
        atomicAdd(&g_deg[d.y], 1);
        atomicAdd(&g_deg[d.z], 1);
        atomicAdd(&g_deg[d.w], 1);
    }
}

// block-level sums (196 blocks x 512)
__global__ void k_scanA() {
    __shared__ int s[512];
    int i = blockIdx.x * 512 + threadIdx.x;
    int v = (i < N_NODES) ? g_deg[i] : 0;
    s[threadIdx.x] = v;
    __syncthreads();
    for (int off = 256; off > 0; off >>= 1) {
        if (threadIdx.x < off) s[threadIdx.x] += s[threadIdx.x + off];
        __syncthreads();
    }
    if (threadIdx.x == 0) g_bsum[blockIdx.x] = s[0];
}

// parallel scan of 196 block sums (was serial: 14us -> ~2us)
__global__ void k_scanB(int nb) {
    __shared__ int s[256];
    int t = threadIdx.x;
    int v = (t < nb) ? g_bsum[t] : 0;
    s[t] = v;
    __syncthreads();
    for (int off = 1; off < 256; off <<= 1) {
        int tv = (t >= off) ? s[t - off] : 0;
        __syncthreads();
        s[t] += tv;
        __syncthreads();
    }
    if (t < nb) g_boff[t] = s[t] - v;                 // exclusive
    if (t == nb - 1) g_rowptr[N_NODES] = s[t];        // total == N_EDGES
}

__global__ void k_scanC() {
    __shared__ int s[512];
    int tid = threadIdx.x;
    int i = blockIdx.x * 512 + tid;
    int v = (i < N_NODES) ? g_deg[i] : 0;
    s[tid] = v;
    __syncthreads();
    for (int off = 1; off < 512; off <<= 1) {
        int t = (tid >= off) ? s[tid - off] : 0;
        __syncthreads();
        s[tid] += t;
        __syncthreads();
    }
    if (i < N_NODES) {
        int excl = s[tid] - v + g_boff[blockIdx.x];
        g_rowptr[i] = excl;
        g_cursor[i] = excl;
    }
}

__global__ void k_fill(const int* __restrict__ src, const int* __restrict__ dst) {
    int e = blockIdx.x * blockDim.x + threadIdx.x;
    if (e * 4 < N_EDGES) {
        int4 s4 = ((const int4*)src)[e];
        int4 d4 = ((const int4*)dst)[e];
        g_eidx[atomicAdd(&g_cursor[d4.x], 1)] = s4.x;
        g_eidx[atomicAdd(&g_cursor[d4.y], 1)] = s4.y;
        g_eidx[atomicAdd(&g_cursor[d4.z], 1)] = s4.z;
        g_eidx[atomicAdd(&g_cursor[d4.w], 1)] = s4.w;
    }
}

// -------- GEMM1: p = x @ [w_self1 | w_neigh1]   (100000 x 128) @ (128 x 32)
// f32x2 packed FFMA along K. block = 128 threads, tile 64 rows x 32 cols, 4x4/thread.
#define XS_STRIDE 130
#define WT_STRIDE 130

__device__ __forceinline__ void ffma2(unsigned long long& acc,
                                      unsigned long long a,
                                      unsigned long long b) {
    asm("fma.rn.f32x2 %0, %1, %2, %0;" : "+l"(acc) : "l"(a), "l"(b));
}

__global__ void __launch_bounds__(128) k_gemm1(const float* __restrict__ x,
                                               const float* __restrict__ wn1,
                                               const float* __restrict__ ws1) {
    __shared__ float xs[64 * XS_STRIDE];
    __shared__ float wt[32 * WT_STRIDE];   // transposed: wt[c*WT_STRIDE + k]
    int tid = threadIdx.x;
    int row0 = blockIdx.x * 64;

    // weights transposed to k-contiguous; cols 0..15 = w_self1, 16..31 = w_neigh1
    for (int i = tid; i < 32 * 128; i += 128) {
        int c = i & 31, k = i >> 5;
        wt[c * WT_STRIDE + k] = (c < 16) ? ws1[k * 16 + c] : wn1[k * 16 + (c - 16)];
    }
    // x tile (coalesced)
    for (int i = tid; i < 64 * 128; i += 128) {
        int r = i >> 7, c = i & 127;
        int gr = row0 + r;
        xs[r * XS_STRIDE + c] = (gr < N_NODES) ? x[gr * 128 + c] : 0.f;
    }
    __syncthreads();

    int cg = tid & 7;          // col group of 4
    int rg = tid >> 3;         // row group of 4 (0..15)
    unsigned long long acc[4][4];
#pragma unroll
    for (int r = 0; r < 4; r++)
#pragma unroll
        for (int c = 0; c < 4; c++) acc[r][c] = 0ULL;

    const float* xp = xs + (rg * 4) * XS_STRIDE;
    const float* wp = wt + (cg * 4) * WT_STRIDE;
#pragma unroll 8
    for (int k = 0; k < 128; k += 2) {
        unsigned long long xv[4], wv[4];
#pragma unroll
        for (int r = 0; r < 4; r++)
            xv[r] = *(const unsigned long long*)(xp + r * XS_STRIDE + k);
#pragma unroll
        for (int c = 0; c < 4; c++)
            wv[c] = *(const unsigned long long*)(wp + c * WT_STRIDE + k);
#pragma unroll
        for (int r = 0; r < 4; r++)
#pragma unroll
            for (int c = 0; c < 4; c++)
                ffma2(acc[r][c], xv[r], wv[c]);
    }
#pragma unroll
    for (int r = 0; r < 4; r++) {
        int gr = row0 + rg * 4 + r;
        if (gr < N_NODES) {
            float4 o;
            float2 a0 = *(float2*)&acc[r][0];
            float2 a1 = *(float2*)&acc[r][1];
            float2 a2 = *(float2*)&acc[r][2];
            float2 a3 = *(float2*)&acc[r][3];
            o.x = a0.x + a0.y;
            o.y = a1.x + a1.y;
            o.z = a2.x + a2.y;
            o.w = a3.x + a3.y;
            *(float4*)(&g_p[gr * 32 + cg * 4]) = o;
        }
    }
}

// -------- layer-1 aggregate + combine + relu --------
// 4 lanes per node, float4 per lane, 4-way edge unroll for MLP
__global__ void __launch_bounds__(256) k_agg1(const float* __restrict__ b1) {
    int t = blockIdx.x * blockDim.x + threadIdx.x;
    int n = t >> 2;
    int fq = t & 3;
    if (n >= N_NODES) return;
    int beg = g_rowptr[n];
    int end = g_rowptr[n + 1];
    float4 acc = make_float4(0.f, 0.f, 0.f, 0.f);
    int i = beg;
    for (; i + 4 <= end; i += 4) {
        int s0 = g_eidx[i], s1 = g_eidx[i + 1], s2 = g_eidx[i + 2], s3 = g_eidx[i + 3];
        float4 v0 = *(const float4*)&g_p[s0 * 32 + 16 + fq * 4];
        float4 v1 = *(const float4*)&g_p[s1 * 32 + 16 + fq * 4];
        float4 v2 = *(const float4*)&g_p[s2 * 32 + 16 + fq * 4];
        float4 v3 = *(const float4*)&g_p[s3 * 32 + 16 + fq * 4];
        acc.x += (v0.x + v1.x) + (v2.x + v3.x);
        acc.y += (v0.y + v1.y) + (v2.y + v3.y);
        acc.z += (v0.z + v1.z) + (v2.z + v3.z);
        acc.w += (v0.w + v1.w) + (v2.w + v3.w);
    }
    for (; i < end; i++) {
        int s = g_eidx[i];
        float4 v = *(const float4*)&g_p[s * 32 + 16 + fq * 4];
        acc.x += v.x; acc.y += v.y; acc.z += v.z; acc.w += v.w;
    }
    float inv = 1.f / fmaxf((float)(end - beg), 1.f);
    float4 self = *(const float4*)&g_p[n * 32 + fq * 4];
    float4 bb = *(const float4*)&b1[fq * 4];
    float4 o;
    o.x = fmaxf(self.x + acc.x * inv + bb.x, 0.f);
    o.y = fmaxf(self.y + acc.y * inv + bb.y, 0.f);
    o.z = fmaxf(self.z + acc.z * inv + bb.z, 0.f);
    o.w = fmaxf(self.w + acc.w * inv + bb.w, 0.f);
    *(float4*)&g_h[n * 16 + fq * 4] = o;
}

// -------- layer-2 aggregate (mean of h over in-neighbors) --------
__global__ void __launch_bounds__(256) k_agg2() {
    int t = blockIdx.x * blockDim.x + threadIdx.x;
    int n = t >> 2;
    int fq = t & 3;
    if (n >= N_NODES) return;
    int beg = g_rowptr[n];
    int end = g_rowptr[n + 1];
    float4 acc = make_float4(0.f, 0.f, 0.f, 0.f);
    int i = beg;
    for (; i + 4 <= end; i += 4) {
        int s0 = g_eidx[i], s1 = g_eidx[i + 1], s2 = g_eidx[i + 2], s3 = g_eidx[i + 3];
        float4 v0 = *(const float4*)&g_h[s0 * 16 + fq * 4];
        float4 v1 = *(const float4*)&g_h[s1 * 16 + fq * 4];
        float4 v2 = *(const float4*)&g_h[s2 * 16 + fq * 4];
        float4 v3 = *(const float4*)&g_h[s3 * 16 + fq * 4];
        acc.x += (v0.x + v1.x) + (v2.x + v3.x);
        acc.y += (v0.y + v1.y) + (v2.y + v3.y);
        acc.z += (v0.z + v1.z) + (v2.z + v3.z);
        acc.w += (v0.w + v1.w) + (v2.w + v3.w);
    }
    for (; i < end; i++) {
        int s = g_eidx[i];
        float4 v = *(const float4*)&g_h[s * 16 + fq * 4];
        acc.x += v.x; acc.y += v.y; acc.z += v.z; acc.w += v.w;
    }
    float inv = 1.f / fmaxf((float)(end - beg), 1.f);
    float4 o;
    o.x = acc.x * inv; o.y = acc.y * inv; o.z = acc.z * inv; o.w = acc.w * inv;
    *(float4*)&g_m2[n * 16 + fq * 4] = o;
}

// -------- output: out = h @ w_self2 + m2 @ w_neigh2 + b2 --------
// block = 320 threads = 8 nodes x 40 classes
__global__ void __launch_bounds__(320) k_out(const float* __restrict__ wn2,
                                             const float* __restrict__ ws2,
                                             const float* __restrict__ b2,
                                             float* __restrict__ out) {
    __shared__ float sws[16 * 40];
    __shared__ float swn[16 * 40];
    __shared__ float sb[40];
    __shared__ float hr[8][16];
    __shared__ float mr[8][16];
    int tid = threadIdx.x;
    for (int i = tid; i < 640; i += 320) { sws[i] = ws2[i]; swn[i] = wn2[i]; }
    if (tid < 40) sb[tid] = b2[tid];
    int n0 = blockIdx.x * 8;
    if (tid < 128) {
        int nl = tid >> 4, f = tid & 15;
        int n = n0 + nl;
        hr[nl][f] = (n < N_NODES) ? g_h[n * 16 + f] : 0.f;
    } else if (tid < 256) {
        int t = tid - 128;
        int nl = t >> 4, f = t & 15;
        int n = n0 + nl;
        mr[nl][f] = (n < N_NODES) ? g_m2[n * 16 + f] : 0.f;
    }
    __syncthreads();
    int c = tid % 40;
    int nl = tid / 40;
    int n = n0 + nl;
    if (n < N_NODES) {
        float acc = sb[c];
#pragma unroll
        for (int k = 0; k < 16; k++)
            acc += hr[nl][k] * sws[k * 40 + c] + mr[nl][k] * swn[k * 40 + c];
        out[n * 40 + c] = acc;
    }
}

extern "C" void kernel_launch(void* const* d_in, const int* in_sizes, int n_in,
                              void* d_out, int out_size) {
    const float* x   = (const float*)d_in[0];
    const int*   src = (const int*)d_in[1];
    const int*   dst = (const int*)d_in[2];
    const float* wn1 = (const float*)d_in[3];
    const float* ws1 = (const float*)d_in[4];
    const float* b1  = (const float*)d_in[5];
    const float* wn2 = (const float*)d_in[6];
    const float* ws2 = (const float*)d_in[7];
    const float* b2  = (const float*)d_in[8];
    float* out = (float*)d_out;

    void* degp = nullptr;
    cudaGetSymbolAddress(&degp, g_deg);
    cudaMemsetAsync(degp, 0, N_NODES * sizeof(int));

    k_count<<<(N_EDGES / 4 + 255) / 256, 256>>>(dst);
    k_scanA<<<196, 512>>>();
    k_scanB<<<1, 256>>>(196);
    k_scanC<<<196, 512>>>();
    k_fill<<<(N_EDGES / 4 + 255) / 256, 256>>>(src, dst);
    k_gemm1<<<(N_NODES + 63) / 64, 128>>>(x, wn1, ws1);
    k_agg1<<<(N_NODES * 4 + 255) / 256, 256>>>(b1);
    k_agg2<<<(N_NODES * 4 + 255) / 256, 256>>>();
    k_out<<<(N_NODES + 7) / 8, 320>>>(wn2, ws2, b2, out);
}

// round 3
// speedup vs baseline: 1.1370x; 1.0683x over previous
#include <cuda_runtime.h>
#include <cuda_bf16.h>

#define N_NODES 100000
#define N_EDGES 1600000
#define NFEAT   128
#define NHID    16
#define NCLS    40
#define NSCAN_BLOCKS 196

// -------- scratch (device globals) --------
__device__ float g_p[N_NODES * 32];    // [:,0:16] = x@w_self1, [:,16:32] = x@w_neigh1
__device__ float g_h[N_NODES * 16];    // layer-1 output (post relu)
__device__ int   g_deg[N_NODES];
__device__ int   g_rowptr[N_NODES + 1];
__device__ int   g_cursor[N_NODES];
__device__ int   g_eidx[N_EDGES];      // src ids grouped by dst (CSR)
__device__ unsigned long long g_scanstate[NSCAN_BLOCKS];  // flag(hi32) | value(lo32)

// -------- CSR: count in-degrees (also re-zeroes scan state for this call) ----
__global__ void k_count(const int* __restrict__ dst) {
    if (blockIdx.x == 0 && threadIdx.x < NSCAN_BLOCKS)
        *(volatile unsigned long long*)&g_scanstate[threadIdx.x] = 0ULL;
    int e = blockIdx.x * blockDim.x + threadIdx.x;
    if (e * 4 < N_EDGES) {
        int4 d = ((const int4*)dst)[e];
        atomicAdd(&g_deg[d.x], 1);
        atomicAdd(&g_deg[d.y], 1);
        atomicAdd(&g_deg[d.z], 1);
        atomicAdd(&g_deg[d.w], 1);
    }
}

__device__ __forceinline__ int warp_sum(int v) {
#pragma unroll
    for (int o = 16; o; o >>= 1) v += __shfl_xor_sync(0xffffffffu, v, o);
    return v;
}

// -------- single-pass exclusive scan over g_deg (decoupled lookback) --------
// 196 blocks x 512 threads; all blocks resident in one wave (no deadlock).
__global__ void __launch_bounds__(512) k_scan() {
    __shared__ int s[512];
    __shared__ int s_prev;
    int b = blockIdx.x, t = threadIdx.x;
    int i = b * 512 + t;
    int v = (i < N_NODES) ? g_deg[i] : 0;
    s[t] = v;
    __syncthreads();
#pragma unroll
    for (int off = 1; off < 512; off <<= 1) {
        int tv = (t >= off) ? s[t - off] : 0;
        __syncthreads();
        s[t] += tv;
        __syncthreads();
    }
    int incl = s[t];
    int blocksum = s[511];

    // publish aggregate (block 0 publishes inclusive prefix directly)
    if (t == 0) {
        unsigned long long pkg = ((b == 0) ? (2ULL << 32) : (1ULL << 32))
                               | (unsigned int)blocksum;
        *(volatile unsigned long long*)&g_scanstate[b] = pkg;
    }

    // lookback (warp 0)
    if (t < 32) {
        int prefix = 0;
        int look = b - 1;
        while (look >= 0) {
            int idx = look - t;
            unsigned long long st = (idx >= 0)
                ? *(volatile unsigned long long*)&g_scanstate[idx]
                : (2ULL << 32);   // beyond block 0: prefix 0
            unsigned int flag = (unsigned int)(st >> 32);
            int val = (int)(st & 0xffffffffu);
            unsigned int nr = __ballot_sync(0xffffffffu, flag == 0u);
            unsigned int pm = __ballot_sync(0xffffffffu, flag == 2u);
            int firstP = pm ? (__ffs(pm) - 1) : 32;
            unsigned int below = (firstP < 32) ? ((1u << firstP) - 1u) : 0xffffffffu;
            if (firstP < 32 && (nr & below) == 0u) {
                int c = (t <= firstP) ? val : 0;
                prefix += warp_sum(c);
                break;
            } else if (nr == 0u) {
                prefix += warp_sum(val);
                look -= 32;
            }
            // else: spin and retry same window
        }
        if (t == 0) {
            s_prev = prefix;
            *(volatile unsigned long long*)&g_scanstate[b] =
                (2ULL << 32) | (unsigned int)(prefix + blocksum);
        }
    }
    __syncthreads();
    int base = s_prev;
    if (i < N_NODES) {
        int excl = base + incl - v;
        g_rowptr[i] = excl;
        g_cursor[i] = excl;
    }
    if (b == NSCAN_BLOCKS - 1 && t == 511)
        g_rowptr[N_NODES] = base + incl;   // == N_EDGES
}

__global__ void k_fill(const int* __restrict__ src, const int* __restrict__ dst) {
    int e = blockIdx.x * blockDim.x + threadIdx.x;
    if (e * 4 < N_EDGES) {
        int4 s4 = ((const int4*)src)[e];
        int4 d4 = ((const int4*)dst)[e];
        g_eidx[atomicAdd(&g_cursor[d4.x], 1)] = s4.x;
        g_eidx[atomicAdd(&g_cursor[d4.y], 1)] = s4.y;
        g_eidx[atomicAdd(&g_cursor[d4.z], 1)] = s4.z;
        g_eidx[atomicAdd(&g_cursor[d4.w], 1)] = s4.w;
    }
}

// -------- GEMM1: p = x @ [w_self1 | w_neigh1]   (100000 x 128) @ (128 x 32)
// f32x2 packed FFMA along K. block = 128 threads, tile 64 rows x 32 cols, 4x4/thread.
#define XS_STRIDE 130
#define WT_STRIDE 130

__device__ __forceinline__ void ffma2(unsigned long long& acc,
                                      unsigned long long a,
                                      unsigned long long b) {
    asm("fma.rn.f32x2 %0, %1, %2, %0;" : "+l"(acc) : "l"(a), "l"(b));
}

__global__ void __launch_bounds__(128) k_gemm1(const float* __restrict__ x,
                                               const float* __restrict__ wn1,
                                               const float* __restrict__ ws1) {
    __shared__ float xs[64 * XS_STRIDE];
    __shared__ float wt[32 * WT_STRIDE];   // transposed: wt[c*WT_STRIDE + k]
    int tid = threadIdx.x;
    int row0 = blockIdx.x * 64;

    for (int i = tid; i < 32 * 128; i += 128) {
        int c = i & 31, k = i >> 5;
        wt[c * WT_STRIDE + k] = (c < 16) ? ws1[k * 16 + c] : wn1[k * 16 + (c - 16)];
    }
    for (int i = tid; i < 64 * 128; i += 128) {
        int r = i >> 7, c = i & 127;
        int gr = row0 + r;
        xs[r * XS_STRIDE + c] = (gr < N_NODES) ? x[gr * 128 + c] : 0.f;
    }
    __syncthreads();

    int cg = tid & 7;
    int rg = tid >> 3;
    unsigned long long acc[4][4];
#pragma unroll
    for (int r = 0; r < 4; r++)
#pragma unroll
        for (int c = 0; c < 4; c++) acc[r][c] = 0ULL;

    const float* xp = xs + (rg * 4) * XS_STRIDE;
    const float* wp = wt + (cg * 4) * WT_STRIDE;
#pragma unroll 8
    for (int k = 0; k < 128; k += 2) {
        unsigned long long xv[4], wv[4];
#pragma unroll
        for (int r = 0; r < 4; r++)
            xv[r] = *(const unsigned long long*)(xp + r * XS_STRIDE + k);
#pragma unroll
        for (int c = 0; c < 4; c++)
            wv[c] = *(const unsigned long long*)(wp + c * WT_STRIDE + k);
#pragma unroll
        for (int r = 0; r < 4; r++)
#pragma unroll
            for (int c = 0; c < 4; c++)
                ffma2(acc[r][c], xv[r], wv[c]);
    }
#pragma unroll
    for (int r = 0; r < 4; r++) {
        int gr = row0 + rg * 4 + r;
        if (gr < N_NODES) {
            float4 o;
            float2 a0 = *(float2*)&acc[r][0];
            float2 a1 = *(float2*)&acc[r][1];
            float2 a2 = *(float2*)&acc[r][2];
            float2 a3 = *(float2*)&acc[r][3];
            o.x = a0.x + a0.y;
            o.y = a1.x + a1.y;
            o.z = a2.x + a2.y;
            o.w = a3.x + a3.y;
            *(float4*)(&g_p[gr * 32 + cg * 4]) = o;
        }
    }
}

// -------- layer-1 aggregate + combine + relu --------
__global__ void __launch_bounds__(256) k_agg1(const float* __restrict__ b1) {
    int t = blockIdx.x * blockDim.x + threadIdx.x;
    int n = t >> 2;
    int fq = t & 3;
    if (n >= N_NODES) return;
    int beg = g_rowptr[n];
    int end = g_rowptr[n + 1];
    float4 acc = make_float4(0.f, 0.f, 0.f, 0.f);
    int i = beg;
    for (; i + 4 <= end; i += 4) {
        int s0 = g_eidx[i], s1 = g_eidx[i + 1], s2 = g_eidx[i + 2], s3 = g_eidx[i + 3];
        float4 v0 = *(const float4*)&g_p[s0 * 32 + 16 + fq * 4];
        float4 v1 = *(const float4*)&g_p[s1 * 32 + 16 + fq * 4];
        float4 v2 = *(const float4*)&g_p[s2 * 32 + 16 + fq * 4];
        float4 v3 = *(const float4*)&g_p[s3 * 32 + 16 + fq * 4];
        acc.x += (v0.x + v1.x) + (v2.x + v3.x);
        acc.y += (v0.y + v1.y) + (v2.y + v3.y);
        acc.z += (v0.z + v1.z) + (v2.z + v3.z);
        acc.w += (v0.w + v1.w) + (v2.w + v3.w);
    }
    for (; i < end; i++) {
        int s = g_eidx[i];
        float4 v = *(const float4*)&g_p[s * 32 + 16 + fq * 4];
        acc.x += v.x; acc.y += v.y; acc.z += v.z; acc.w += v.w;
    }
    float inv = 1.f / fmaxf((float)(end - beg), 1.f);
    float4 self = *(const float4*)&g_p[n * 32 + fq * 4];
    float4 bb = *(const float4*)&b1[fq * 4];
    float4 o;
    o.x = fmaxf(self.x + acc.x * inv + bb.x, 0.f);
    o.y = fmaxf(self.y + acc.y * inv + bb.y, 0.f);
    o.z = fmaxf(self.z + acc.z * inv + bb.z, 0.f);
    o.w = fmaxf(self.w + acc.w * inv + bb.w, 0.f);
    *(float4*)&g_h[n * 16 + fq * 4] = o;
}

// -------- fused layer-2 aggregate + output projection --------
// block = 256 threads = 64 nodes; phase 1: gather mean(h) (4 lanes/node),
// phase 2: project to 40 classes from smem.
__global__ void __launch_bounds__(256) k_agg2out(const float* __restrict__ wn2,
                                                 const float* __restrict__ ws2,
                                                 const float* __restrict__ b2,
                                                 float* __restrict__ out) {
    __shared__ float sw[2 * 640];    // [0:640) ws2, [640:1280) wn2 (k*40+c)
    __shared__ float sb[40];
    __shared__ float4 sh4[64 * 4];   // h   per node (16 floats)
    __shared__ float4 sm4[64 * 4];   // m2  per node (16 floats)
    int t = threadIdx.x;
    for (int i = t; i < 640; i += 256) { sw[i] = ws2[i]; sw[640 + i] = wn2[i]; }
    if (t < 40) sb[t] = b2[t];

    int n0 = blockIdx.x * 64;
    int nl = t >> 2, fq = t & 3;
    int n = n0 + nl;
    float4 acc = make_float4(0.f, 0.f, 0.f, 0.f);
    float4 hv = make_float4(0.f, 0.f, 0.f, 0.f);
    if (n < N_NODES) {
        int beg = g_rowptr[n];
        int end = g_rowptr[n + 1];
        int i = beg;
        for (; i + 4 <= end; i += 4) {
            int s0 = g_eidx[i], s1 = g_eidx[i + 1], s2 = g_eidx[i + 2], s3 = g_eidx[i + 3];
            float4 v0 = *(const float4*)&g_h[s0 * 16 + fq * 4];
            float4 v1 = *(const float4*)&g_h[s1 * 16 + fq * 4];
            float4 v2 = *(const float4*)&g_h[s2 * 16 + fq * 4];
            float4 v3 = *(const float4*)&g_h[s3 * 16 + fq * 4];
            acc.x += (v0.x + v1.x) + (v2.x + v3.x);
            acc.y += (v0.y + v1.y) + (v2.y + v3.y);
            acc.z += (v0.z + v1.z) + (v2.z + v3.z);
            acc.w += (v0.w + v1.w) + (v2.w + v3.w);
        }
        for (; i < end; i++) {
            int s = g_eidx[i];
            float4 v = *(const float4*)&g_h[s * 16 + fq * 4];
            acc.x += v.x; acc.y += v.y; acc.z += v.z; acc.w += v.w;
        }
        float inv = 1.f / fmaxf((float)(end - beg), 1.f);
        acc.x *= inv; acc.y *= inv; acc.z *= inv; acc.w *= inv;
        hv = *(const float4*)&g_h[n * 16 + fq * 4];
    }
    sh4[nl * 4 + fq] = hv;
    sm4[nl * 4 + fq] = acc;
    __syncthreads();

    const float* shf = (const float*)sh4;
    const float* smf = (const float*)sm4;
#pragma unroll
    for (int o = t; o < 64 * 40; o += 256) {
        int n2 = o / 40, c = o % 40;
        int gn = n0 + n2;
        if (gn < N_NODES) {
            float a = sb[c];
#pragma unroll
            for (int k = 0; k < 16; k++)
                a += shf[n2 * 16 + k] * sw[k * 40 + c]
                   + smf[n2 * 16 + k] * sw[640 + k * 40 + c];
            out[gn * 40 + c] = a;
        }
    }
}

extern "C" void kernel_launch(void* const* d_in, const int* in_sizes, int n_in,
                              void* d_out, int out_size) {
    const float* x   = (const float*)d_in[0];
    const int*   src = (const int*)d_in[1];
    const int*   dst = (const int*)d_in[2];
    const float* wn1 = (const float*)d_in[3];
    const float* ws1 = (const float*)d_in[4];
    const float* b1  = (const float*)d_in[5];
    const float* wn2 = (const float*)d_in[6];
    const float* ws2 = (const float*)d_in[7];
    const float* b2  = (const float*)d_in[8];
    float* out = (float*)d_out;

    void* degp = nullptr;
    cudaGetSymbolAddress(&degp, g_deg);
    cudaMemsetAsync(degp, 0, N_NODES * sizeof(int));

    k_count<<<(N_EDGES / 4 + 255) / 256, 256>>>(dst);
    k_scan<<<NSCAN_BLOCKS, 512>>>();
    k_fill<<<(N_EDGES / 4 + 255) / 256, 256>>>(src, dst);
    k_gemm1<<<(N_NODES + 63) / 64, 128>>>(x, wn1, ws1);   // kernel idx 3 -> profiled
    k_agg1<<<(N_NODES * 4 + 255) / 256, 256>>>(b1);
    k_agg2out<<<(N_NODES + 63) / 64, 256>>>(wn2, ws2, b2, out);
}

// round 4
// speedup vs baseline: 1.2978x; 1.1413x over previous
#include <cuda_runtime.h>
#include <cuda_bf16.h>

#define N_NODES 100000
#define N_EDGES 1600000
#define NFEAT   128
#define NHID    16
#define NCLS    40
#define NSCAN_BLOCKS 196

// -------- scratch (device globals) --------
__device__ float g_p[N_NODES * 32];    // [:,0:16] = x@w_self1, [:,16:32] = x@w_neigh1
__device__ float g_h[N_NODES * 16];    // layer-1 output (post relu)
__device__ int   g_deg[N_NODES];
__device__ int   g_rowptr[N_NODES + 1];
__device__ int   g_cursor[N_NODES];
__device__ int   g_eidx[N_EDGES];      // src ids grouped by dst (CSR)
__device__ unsigned long long g_scanstate[NSCAN_BLOCKS];  // flag(hi32) | value(lo32)

// -------- CSR: count in-degrees (also re-zeroes scan state for this call) ----
__global__ void k_count(const int* __restrict__ dst) {
    if (blockIdx.x == 0 && threadIdx.x < NSCAN_BLOCKS)
        *(volatile unsigned long long*)&g_scanstate[threadIdx.x] = 0ULL;
    int e = blockIdx.x * blockDim.x + threadIdx.x;
    if (e * 4 < N_EDGES) {
        int4 d = ((const int4*)dst)[e];
        atomicAdd(&g_deg[d.x], 1);
        atomicAdd(&g_deg[d.y], 1);
        atomicAdd(&g_deg[d.z], 1);
        atomicAdd(&g_deg[d.w], 1);
    }
}

__device__ __forceinline__ int warp_sum(int v) {
#pragma unroll
    for (int o = 16; o; o >>= 1) v += __shfl_xor_sync(0xffffffffu, v, o);
    return v;
}

// -------- single-pass exclusive scan over g_deg (decoupled lookback) --------
__global__ void __launch_bounds__(512) k_scan() {
    __shared__ int s[512];
    __shared__ int s_prev;
    int b = blockIdx.x, t = threadIdx.x;
    int i = b * 512 + t;
    int v = (i < N_NODES) ? g_deg[i] : 0;
    s[t] = v;
    __syncthreads();
#pragma unroll
    for (int off = 1; off < 512; off <<= 1) {
        int tv = (t >= off) ? s[t - off] : 0;
        __syncthreads();
        s[t] += tv;
        __syncthreads();
    }
    int incl = s[t];
    int blocksum = s[511];

    if (t == 0) {
        unsigned long long pkg = ((b == 0) ? (2ULL << 32) : (1ULL << 32))
                               | (unsigned int)blocksum;
        *(volatile unsigned long long*)&g_scanstate[b] = pkg;
    }

    if (t < 32) {
        int prefix = 0;
        int look = b - 1;
        while (look >= 0) {
            int idx = look - t;
            unsigned long long st = (idx >= 0)
                ? *(volatile unsigned long long*)&g_scanstate[idx]
                : (2ULL << 32);
            unsigned int flag = (unsigned int)(st >> 32);
            int val = (int)(st & 0xffffffffu);
            unsigned int nr = __ballot_sync(0xffffffffu, flag == 0u);
            unsigned int pm = __ballot_sync(0xffffffffu, flag == 2u);
            int firstP = pm ? (__ffs(pm) - 1) : 32;
            unsigned int below = (firstP < 32) ? ((1u << firstP) - 1u) : 0xffffffffu;
            if (firstP < 32 && (nr & below) == 0u) {
                int c = (t <= firstP) ? val : 0;
                prefix += warp_sum(c);
                break;
            } else if (nr == 0u) {
                prefix += warp_sum(val);
                look -= 32;
            }
        }
        if (t == 0) {
            s_prev = prefix;
            *(volatile unsigned long long*)&g_scanstate[b] =
                (2ULL << 32) | (unsigned int)(prefix + blocksum);
        }
    }
    __syncthreads();
    int base = s_prev;
    if (i < N_NODES) {
        int excl = base + incl - v;
        g_rowptr[i] = excl;
        g_cursor[i] = excl;
    }
    if (b == NSCAN_BLOCKS - 1 && t == 511)
        g_rowptr[N_NODES] = base + incl;
}

__global__ void k_fill(const int* __restrict__ src, const int* __restrict__ dst) {
    int e = blockIdx.x * blockDim.x + threadIdx.x;
    if (e * 4 < N_EDGES) {
        int4 s4 = ((const int4*)src)[e];
        int4 d4 = ((const int4*)dst)[e];
        g_eidx[atomicAdd(&g_cursor[d4.x], 1)] = s4.x;
        g_eidx[atomicAdd(&g_cursor[d4.y], 1)] = s4.y;
        g_eidx[atomicAdd(&g_cursor[d4.z], 1)] = s4.z;
        g_eidx[atomicAdd(&g_cursor[d4.w], 1)] = s4.w;
    }
}

// ===================== GEMM1 =====================
// p = x @ [w_self1 | w_neigh1]   (100000 x 128) @ (128 x 32)
// 256 threads, tile 128 rows x 32 cols, 4x4 per thread, f32x2 FFMA.
// K processed in 4 chunks of 32; next chunk prefetched into registers.
// Weight layout: wt2[(k4*4 + c)*8 + cg] as float4 = W[k4*4+0..3][cg*4+c]
//   -> an LDS.128 across the 8 cg lane-groups reads 128B contiguous (no conflicts).
#define XS_STRIDE 36   // floats; multiple of 4 (16B alignment for LDS.128)

__device__ __forceinline__ void ffma2(unsigned long long& acc,
                                      unsigned long long a,
                                      unsigned long long b) {
    asm("fma.rn.f32x2 %0, %1, %2, %0;" : "+l"(acc) : "l"(a), "l"(b));
}

__global__ void __launch_bounds__(256) k_gemm1(const float* __restrict__ x,
                                               const float* __restrict__ wn1,
                                               const float* __restrict__ ws1) {
    __shared__ __align__(16) float xs[128 * XS_STRIDE];   // 18.4 KB
    __shared__ __align__(16) float wt2[4096];             // 16.4 KB
    int tid = threadIdx.x;
    int row0 = blockIdx.x * 128;

    // pack weights: dest offset i = ((k4*4 + c)*8 + cg)*4 + j
    for (int i = tid; i < 4096; i += 256) {
        int j  = i & 3;
        int cg = (i >> 2) & 7;
        int c  = (i >> 5) & 3;
        int k4 = i >> 7;
        int col = cg * 4 + c;
        int k   = k4 * 4 + j;
        wt2[i] = (col < 16) ? ws1[k * 16 + col] : wn1[k * 16 + (col - 16)];
    }

    int cg = tid & 7;          // col group (0..7)
    int rg = tid >> 3;         // row group (0..31)
    unsigned long long acc[4][4];
#pragma unroll
    for (int r = 0; r < 4; r++)
#pragma unroll
        for (int c = 0; c < 4; c++) acc[r][c] = 0ULL;

    // prefetch chunk 0 into registers
    float4 xreg[4];
    {
        int fr = tid >> 3, fc = tid & 7;     // row fr, float4-col fc within chunk
#pragma unroll
        for (int q = 0; q < 4; q++) {
            int r = fr + q * 32;
            int gr = row0 + r;
            xreg[q] = (gr < N_NODES)
                ? *(const float4*)(x + gr * 128 + 0 * 32 + fc * 4)
                : make_float4(0.f, 0.f, 0.f, 0.f);
        }
    }

    const float* xp = xs + (rg * 4) * XS_STRIDE;

#pragma unroll
    for (int chunk = 0; chunk < 4; chunk++) {
        __syncthreads();   // xs readers of previous chunk done
        {
            int fr = tid >> 3, fc = tid & 7;
#pragma unroll
            for (int q = 0; q < 4; q++) {
                int r = fr + q * 32;
                *(float4*)(xs + r * XS_STRIDE + fc * 4) = xreg[q];
            }
        }
        __syncthreads();
        if (chunk < 3) {
            int fr = tid >> 3, fc = tid & 7;
#pragma unroll
            for (int q = 0; q < 4; q++) {
                int r = fr + q * 32;
                int gr = row0 + r;
                xreg[q] = (gr < N_NODES)
                    ? *(const float4*)(x + gr * 128 + (chunk + 1) * 32 + fc * 4)
                    : make_float4(0.f, 0.f, 0.f, 0.f);
            }
        }

#pragma unroll
        for (int k4 = 0; k4 < 8; k4++) {
            int k4g = chunk * 8 + k4;
            const float* wbase = wt2 + ((k4g * 4) * 8 + cg) * 4;
            ulonglong2 wv[4], xv[4];
#pragma unroll
            for (int c = 0; c < 4; c++)
                wv[c] = *(const ulonglong2*)(wbase + c * 32);
#pragma unroll
            for (int r = 0; r < 4; r++)
                xv[r] = *(const ulonglong2*)(xp + r * XS_STRIDE + k4 * 4);
#pragma unroll
            for (int r = 0; r < 4; r++)
#pragma unroll
                for (int c = 0; c < 4; c++)
                    ffma2(acc[r][c], xv[r].x, wv[c].x);
#pragma unroll
            for (int r = 0; r < 4; r++)
#pragma unroll
                for (int c = 0; c < 4; c++)
                    ffma2(acc[r][c], xv[r].y, wv[c].y);
        }
    }

#pragma unroll
    for (int r = 0; r < 4; r++) {
        int gr = row0 + rg * 4 + r;
        if (gr < N_NODES) {
            float2 a0 = *(float2*)&acc[r][0];
            float2 a1 = *(float2*)&acc[r][1];
            float2 a2 = *(float2*)&acc[r][2];
            float2 a3 = *(float2*)&acc[r][3];
            float4 o;
            o.x = a0.x + a0.y;
            o.y = a1.x + a1.y;
            o.z = a2.x + a2.y;
            o.w = a3.x + a3.y;
            *(float4*)(&g_p[gr * 32 + cg * 4]) = o;
        }
    }
}

// -------- layer-1 aggregate + combine + relu --------
__global__ void __launch_bounds__(256) k_agg1(const float* __restrict__ b1) {
    int t = blockIdx.x * blockDim.x + threadIdx.x;
    int n = t >> 2;
    int fq = t & 3;
    if (n >= N_NODES) return;
    int beg = g_rowptr[n];
    int end = g_rowptr[n + 1];
    float4 acc = make_float4(0.f, 0.f, 0.f, 0.f);
    int i = beg;
    for (; i + 4 <= end; i += 4) {
        int s0 = g_eidx[i], s1 = g_eidx[i + 1], s2 = g_eidx[i + 2], s3 = g_eidx[i + 3];
        float4 v0 = *(const float4*)&g_p[s0 * 32 + 16 + fq * 4];
        float4 v1 = *(const float4*)&g_p[s1 * 32 + 16 + fq * 4];
        float4 v2 = *(const float4*)&g_p[s2 * 32 + 16 + fq * 4];
        float4 v3 = *(const float4*)&g_p[s3 * 32 + 16 + fq * 4];
        acc.x += (v0.x + v1.x) + (v2.x + v3.x);
        acc.y += (v0.y + v1.y) + (v2.y + v3.y);
        acc.z += (v0.z + v1.z) + (v2.z + v3.z);
        acc.w += (v0.w + v1.w) + (v2.w + v3.w);
    }
    for (; i < end; i++) {
        int s = g_eidx[i];
        float4 v = *(const float4*)&g_p[s * 32 + 16 + fq * 4];
        acc.x += v.x; acc.y += v.y; acc.z += v.z; acc.w += v.w;
    }
    float inv = 1.f / fmaxf((float)(end - beg), 1.f);
    float4 self = *(const float4*)&g_p[n * 32 + fq * 4];
    float4 bb = *(const float4*)&b1[fq * 4];
    float4 o;
    o.x = fmaxf(self.x + acc.x * inv + bb.x, 0.f);
    o.y = fmaxf(self.y + acc.y * inv + bb.y, 0.f);
    o.z = fmaxf(self.z + acc.z * inv + bb.z, 0.f);
    o.w = fmaxf(self.w + acc.w * inv + bb.w, 0.f);
    *(float4*)&g_h[n * 16 + fq * 4] = o;
}

// -------- fused layer-2 aggregate + output projection --------
__global__ void __launch_bounds__(256) k_agg2out(const float* __restrict__ wn2,
                                                 const float* __restrict__ ws2,
                                                 const float* __restrict__ b2,
                                                 float* __restrict__ out) {
    __shared__ float sw[2 * 640];
    __shared__ float sb[40];
    __shared__ float4 sh4[64 * 4];
    __shared__ float4 sm4[64 * 4];
    int t = threadIdx.x;
    for (int i = t; i < 640; i += 256) { sw[i] = ws2[i]; sw[640 + i] = wn2[i]; }
    if (t < 40) sb[t] = b2[t];

    int n0 = blockIdx.x * 64;
    int nl = t >> 2, fq = t & 3;
    int n = n0 + nl;
    float4 acc = make_float4(0.f, 0.f, 0.f, 0.f);
    float4 hv = make_float4(0.f, 0.f, 0.f, 0.f);
    if (n < N_NODES) {
        int beg = g_rowptr[n];
        int end = g_rowptr[n + 1];
        int i = beg;
        for (; i + 4 <= end; i += 4) {
            int s0 = g_eidx[i], s1 = g_eidx[i + 1], s2 = g_eidx[i + 2], s3 = g_eidx[i + 3];
            float4 v0 = *(const float4*)&g_h[s0 * 16 + fq * 4];
            float4 v1 = *(const float4*)&g_h[s1 * 16 + fq * 4];
            float4 v2 = *(const float4*)&g_h[s2 * 16 + fq * 4];
            float4 v3 = *(const float4*)&g_h[s3 * 16 + fq * 4];
            acc.x += (v0.x + v1.x) + (v2.x + v3.x);
            acc.y += (v0.y + v1.y) + (v2.y + v3.y);
            acc.z += (v0.z + v1.z) + (v2.z + v3.z);
            acc.w += (v0.w + v1.w) + (v2.w + v3.w);
        }
        for (; i < end; i++) {
            int s = g_eidx[i];
            float4 v = *(const float4*)&g_h[s * 16 + fq * 4];
            acc.x += v.x; acc.y += v.y; acc.z += v.z; acc.w += v.w;
        }
        float inv = 1.f / fmaxf((float)(end - beg), 1.f);
        acc.x *= inv; acc.y *= inv; acc.z *= inv; acc.w *= inv;
        hv = *(const float4*)&g_h[n * 16 + fq * 4];
    }
    sh4[nl * 4 + fq] = hv;
    sm4[nl * 4 + fq] = acc;
    __syncthreads();

    const float* shf = (const float*)sh4;
    const float* smf = (const float*)sm4;
#pragma unroll
    for (int o = t; o < 64 * 40; o += 256) {
        int n2 = o / 40, c = o % 40;
        int gn = n0 + n2;
        if (gn < N_NODES) {
            float a = sb[c];
#pragma unroll
            for (int k = 0; k < 16; k++)
                a += shf[n2 * 16 + k] * sw[k * 40 + c]
                   + smf[n2 * 16 + k] * sw[640 + k * 40 + c];
            out[gn * 40 + c] = a;
        }
    }
}

extern "C" void kernel_launch(void* const* d_in, const int* in_sizes, int n_in,
                              void* d_out, int out_size) {
    const float* x   = (const float*)d_in[0];
    const int*   src = (const int*)d_in[1];
    const int*   dst = (const int*)d_in[2];
    const float* wn1 = (const float*)d_in[3];
    const float* ws1 = (const float*)d_in[4];
    const float* b1  = (const float*)d_in[5];
    const float* wn2 = (const float*)d_in[6];
    const float* ws2 = (const float*)d_in[7];
    const float* b2  = (const float*)d_in[8];
    float* out = (float*)d_out;

    void* degp = nullptr;
    cudaGetSymbolAddress(&degp, g_deg);
    cudaMemsetAsync(degp, 0, N_NODES * sizeof(int));

    k_count<<<(N_EDGES / 4 + 255) / 256, 256>>>(dst);
    k_scan<<<NSCAN_BLOCKS, 512>>>();
    k_fill<<<(N_EDGES / 4 + 255) / 256, 256>>>(src, dst);
    k_gemm1<<<(N_NODES + 127) / 128, 256>>>(x, wn1, ws1);
    k_agg1<<<(N_NODES * 4 + 255) / 256, 256>>>(b1);
    k_agg2out<<<(N_NODES + 63) / 64, 256>>>(wn2, ws2, b2, out);
}

// round 5
// speedup vs baseline: 1.3258x; 1.0216x over previous
#include <cuda_runtime.h>
#include <cuda_bf16.h>
#include <cuda_pipeline.h>

#define N_NODES 100000
#define N_EDGES 1600000
#define NFEAT   128
#define NHID    16
#define NCLS    40
#define NSCAN_BLOCKS 196

// -------- scratch (device globals) --------
__device__ float g_p[N_NODES * 32];    // [:,0:16] = x@w_self1, [:,16:32] = x@w_neigh1
__device__ float g_h[N_NODES * 16];    // layer-1 output (post relu)
__device__ int   g_deg[N_NODES];
__device__ int   g_rowptr[N_NODES + 1];
__device__ int   g_cursor[N_NODES];
__device__ int   g_eidx[N_EDGES];      // src ids grouped by dst (CSR)
__device__ unsigned long long g_scanstate[NSCAN_BLOCKS];  // flag(hi32) | value(lo32)

// -------- CSR: count in-degrees (also re-zeroes scan state for this call) ----
__global__ void k_count(const int* __restrict__ dst) {
    if (blockIdx.x == 0 && threadIdx.x < NSCAN_BLOCKS)
        *(volatile unsigned long long*)&g_scanstate[threadIdx.x] = 0ULL;
    int e = blockIdx.x * blockDim.x + threadIdx.x;
    if (e * 4 < N_EDGES) {
        int4 d = ((const int4*)dst)[e];
        atomicAdd(&g_deg[d.x], 1);
        atomicAdd(&g_deg[d.y], 1);
        atomicAdd(&g_deg[d.z], 1);
        atomicAdd(&g_deg[d.w], 1);
    }
}

__device__ __forceinline__ int warp_sum(int v) {
#pragma unroll
    for (int o = 16; o; o >>= 1) v += __shfl_xor_sync(0xffffffffu, v, o);
    return v;
}

// -------- single-pass exclusive scan over g_deg (decoupled lookback) --------
__global__ void __launch_bounds__(512) k_scan() {
    __shared__ int s[512];
    __shared__ int s_prev;
    int b = blockIdx.x, t = threadIdx.x;
    int i = b * 512 + t;
    int v = (i < N_NODES) ? g_deg[i] : 0;
    s[t] = v;
    __syncthreads();
#pragma unroll
    for (int off = 1; off < 512; off <<= 1) {
        int tv = (t >= off) ? s[t - off] : 0;
        __syncthreads();
        s[t] += tv;
        __syncthreads();
    }
    int incl = s[t];
    int blocksum = s[511];

    if (t == 0) {
        unsigned long long pkg = ((b == 0) ? (2ULL << 32) : (1ULL << 32))
                               | (unsigned int)blocksum;
        *(volatile unsigned long long*)&g_scanstate[b] = pkg;
    }

    if (t < 32) {
        int prefix = 0;
        int look = b - 1;
        while (look >= 0) {
            int idx = look - t;
            unsigned long long st = (idx >= 0)
                ? *(volatile unsigned long long*)&g_scanstate[idx]
                : (2ULL << 32);
            unsigned int flag = (unsigned int)(st >> 32);
            int val = (int)(st & 0xffffffffu);
            unsigned int nr = __ballot_sync(0xffffffffu, flag == 0u);
            unsigned int pm = __ballot_sync(0xffffffffu, flag == 2u);
            int firstP = pm ? (__ffs(pm) - 1) : 32;
            unsigned int below = (firstP < 32) ? ((1u << firstP) - 1u) : 0xffffffffu;
            if (firstP < 32 && (nr & below) == 0u) {
                int c = (t <= firstP) ? val : 0;
                prefix += warp_sum(c);
                break;
            } else if (nr == 0u) {
                prefix += warp_sum(val);
                look -= 32;
            }
        }
        if (t == 0) {
            s_prev = prefix;
            *(volatile unsigned long long*)&g_scanstate[b] =
                (2ULL << 32) | (unsigned int)(prefix + blocksum);
        }
    }
    __syncthreads();
    int base = s_prev;
    if (i < N_NODES) {
        int excl = base + incl - v;
        g_rowptr[i] = excl;
        g_cursor[i] = excl;
    }
    if (b == NSCAN_BLOCKS - 1 && t == 511)
        g_rowptr[N_NODES] = base + incl;
}

__global__ void k_fill(const int* __restrict__ src, const int* __restrict__ dst) {
    int e = blockIdx.x * blockDim.x + threadIdx.x;
    if (e * 4 < N_EDGES) {
        int4 s4 = ((const int4*)src)[e];
        int4 d4 = ((const int4*)dst)[e];
        g_eidx[atomicAdd(&g_cursor[d4.x], 1)] = s4.x;
        g_eidx[atomicAdd(&g_cursor[d4.y], 1)] = s4.y;
        g_eidx[atomicAdd(&g_cursor[d4.z], 1)] = s4.z;
        g_eidx[atomicAdd(&g_cursor[d4.w], 1)] = s4.w;
    }
}

// ===================== GEMM1 =====================
// p = x @ [w_self1 | w_neigh1]   (100000 x 128) @ (128 x 32)
// 256 threads, tile 256 rows x 32 cols; per-thread 4 rows x 8 cols; f32x2 FFMA
// along K. K staged in 4 chunks of 32 via cp.async.
// xs stride 36 floats -> reader lanes (8 distinct rg per warp) conflict-free.
// wt2 layout [k4][c][cg][j]: value = W[k4*4+j][cg*8+c]; 4 cg lanes read 64B
// contiguous, 8-lane broadcast.
#define XS_STRIDE 36

__device__ __forceinline__ void ffma2(unsigned long long& acc,
                                      unsigned long long a,
                                      unsigned long long b) {
    asm("fma.rn.f32x2 %0, %1, %2, %0;" : "+l"(acc) : "l"(a), "l"(b));
}

__global__ void __launch_bounds__(256, 2) k_gemm1(const float* __restrict__ x,
                                                  const float* __restrict__ wn1,
                                                  const float* __restrict__ ws1) {
    __shared__ __align__(16) float xs[256 * XS_STRIDE];   // 36 KB
    __shared__ __align__(16) float wt2[4096];             // 16 KB
    int tid = threadIdx.x;
    int row0 = blockIdx.x * 256;

    // pack weights: wt2[k4g*128 + c*16 + cg*4 + j] = W[k4g*4+j][cg*8+c]
    for (int i = tid; i < 4096; i += 256) {
        int j   = i & 3;
        int cg  = (i >> 2) & 3;
        int c   = (i >> 4) & 7;
        int k4g = i >> 7;
        int col = cg * 8 + c;
        int k   = k4g * 4 + j;
        wt2[i] = (col < 16) ? ws1[k * 16 + col] : wn1[k * 16 + (col - 16)];
    }

    int cg = tid & 3;        // col group (0..3), 8 cols each
    int rg = tid >> 2;       // row group (0..63), rows rg + q*64

    unsigned long long acc[4][8];
#pragma unroll
    for (int q = 0; q < 4; q++)
#pragma unroll
        for (int c = 0; c < 8; c++) acc[q][c] = 0ULL;

#pragma unroll
    for (int chunk = 0; chunk < 4; chunk++) {
        __syncthreads();   // previous chunk's readers done
        // stage 256 rows x 32 floats: 8 x 16B per thread, fully coalesced
#pragma unroll
        for (int l = 0; l < 8; l++) {
            int f = l * 256 + tid;        // float4 index
            int row = f >> 3, slot = f & 7;
            int gr = row0 + row;
            if (gr >= N_NODES) gr = N_NODES - 1;   // clamp; stores are guarded
            __pipeline_memcpy_async(&xs[row * XS_STRIDE + slot * 4],
                                    &x[gr * 128 + chunk * 32 + slot * 4], 16);
        }
        __pipeline_commit();
        __pipeline_wait_prior(0);
        __syncthreads();

#pragma unroll
        for (int k4 = 0; k4 < 8; k4++) {
            int k4g = chunk * 8 + k4;
            const float* wbase = wt2 + k4g * 128 + cg * 4;
            ulonglong2 xv[4];
#pragma unroll
            for (int q = 0; q < 4; q++)
                xv[q] = *(const ulonglong2*)&xs[(rg + q * 64) * XS_STRIDE + k4 * 4];
#pragma unroll
            for (int ch = 0; ch < 2; ch++) {   // split cols 0..3 / 4..7 (reg pressure)
                ulonglong2 wv[4];
#pragma unroll
                for (int c = 0; c < 4; c++)
                    wv[c] = *(const ulonglong2*)(wbase + (ch * 4 + c) * 16);
#pragma unroll
                for (int q = 0; q < 4; q++)
#pragma unroll
                    for (int c = 0; c < 4; c++)
                        ffma2(acc[q][ch * 4 + c], xv[q].x, wv[c].x);
#pragma unroll
                for (int q = 0; q < 4; q++)
#pragma unroll
                    for (int c = 0; c < 4; c++)
                        ffma2(acc[q][ch * 4 + c], xv[q].y, wv[c].y);
            }
        }
    }

#pragma unroll
    for (int q = 0; q < 4; q++) {
        int gr = row0 + rg + q * 64;
        if (gr < N_NODES) {
            float o[8];
#pragma unroll
            for (int c = 0; c < 8; c++) {
                float2 a = *(float2*)&acc[q][c];
                o[c] = a.x + a.y;
            }
            *(float4*)(&g_p[gr * 32 + cg * 8])     = make_float4(o[0], o[1], o[2], o[3]);
            *(float4*)(&g_p[gr * 32 + cg * 8 + 4]) = make_float4(o[4], o[5], o[6], o[7]);
        }
    }
}

// -------- layer-1 aggregate + combine + relu --------
__global__ void __launch_bounds__(256) k_agg1(const float* __restrict__ b1) {
    int t = blockIdx.x * blockDim.x + threadIdx.x;
    int n = t >> 2;
    int fq = t & 3;
    if (n >= N_NODES) return;
    int beg = g_rowptr[n];
    int end = g_rowptr[n + 1];
    float4 acc = make_float4(0.f, 0.f, 0.f, 0.f);
    int i = beg;
    for (; i + 4 <= end; i += 4) {
        int s0 = g_eidx[i], s1 = g_eidx[i + 1], s2 = g_eidx[i + 2], s3 = g_eidx[i + 3];
        float4 v0 = *(const float4*)&g_p[s0 * 32 + 16 + fq * 4];
        float4 v1 = *(const float4*)&g_p[s1 * 32 + 16 + fq * 4];
        float4 v2 = *(const float4*)&g_p[s2 * 32 + 16 + fq * 4];
        float4 v3 = *(const float4*)&g_p[s3 * 32 + 16 + fq * 4];
        acc.x += (v0.x + v1.x) + (v2.x + v3.x);
        acc.y += (v0.y + v1.y) + (v2.y + v3.y);
        acc.z += (v0.z + v1.z) + (v2.z + v3.z);
        acc.w += (v0.w + v1.w) + (v2.w + v3.w);
    }
    for (; i < end; i++) {
        int s = g_eidx[i];
        float4 v = *(const float4*)&g_p[s * 32 + 16 + fq * 4];
        acc.x += v.x; acc.y += v.y; acc.z += v.z; acc.w += v.w;
    }
    float inv = 1.f / fmaxf((float)(end - beg), 1.f);
    float4 self = *(const float4*)&g_p[n * 32 + fq * 4];
    float4 bb = *(const float4*)&b1[fq * 4];
    float4 o;
    o.x = fmaxf(self.x + acc.x * inv + bb.x, 0.f);
    o.y = fmaxf(self.y + acc.y * inv + bb.y, 0.f);
    o.z = fmaxf(self.z + acc.z * inv + bb.z, 0.f);
    o.w = fmaxf(self.w + acc.w * inv + bb.w, 0.f);
    *(float4*)&g_h[n * 16 + fq * 4] = o;
}

// -------- fused layer-2 aggregate + output projection --------
__global__ void __launch_bounds__(256) k_agg2out(const float* __restrict__ wn2,
                                                 const float* __restrict__ ws2,
                                                 const float* __restrict__ b2,
                                                 float* __restrict__ out) {
    __shared__ float sw[2 * 640];
    __shared__ float sb[40];
    __shared__ float4 sh4[64 * 4];
    __shared__ float4 sm4[64 * 4];
    int t = threadIdx.x;
    for (int i = t; i < 640; i += 256) { sw[i] = ws2[i]; sw[640 + i] = wn2[i]; }
    if (t < 40) sb[t] = b2[t];

    int n0 = blockIdx.x * 64;
    int nl = t >> 2, fq = t & 3;
    int n = n0 + nl;
    float4 acc = make_float4(0.f, 0.f, 0.f, 0.f);
    float4 hv = make_float4(0.f, 0.f, 0.f, 0.f);
    if (n < N_NODES) {
        int beg = g_rowptr[n];
        int end = g_rowptr[n + 1];
        int i = beg;
        for (; i + 4 <= end; i += 4) {
            int s0 = g_eidx[i], s1 = g_eidx[i + 1], s2 = g_eidx[i + 2], s3 = g_eidx[i + 3];
            float4 v0 = *(const float4*)&g_h[s0 * 16 + fq * 4];
            float4 v1 = *(const float4*)&g_h[s1 * 16 + fq * 4];
            float4 v2 = *(const float4*)&g_h[s2 * 16 + fq * 4];
            float4 v3 = *(const float4*)&g_h[s3 * 16 + fq * 4];
            acc.x += (v0.x + v1.x) + (v2.x + v3.x);
            acc.y += (v0.y + v1.y) + (v2.y + v3.y);
            acc.z += (v0.z + v1.z) + (v2.z + v3.z);
            acc.w += (v0.w + v1.w) + (v2.w + v3.w);
        }
        for (; i < end; i++) {
            int s = g_eidx[i];
            float4 v = *(const float4*)&g_h[s * 16 + fq * 4];
            acc.x += v.x; acc.y += v.y; acc.z += v.z; acc.w += v.w;
        }
        float inv = 1.f / fmaxf((float)(end - beg), 1.f);
        acc.x *= inv; acc.y *= inv; acc.z *= inv; acc.w *= inv;
        hv = *(const float4*)&g_h[n * 16 + fq * 4];
    }
    sh4[nl * 4 + fq] = hv;
    sm4[nl * 4 + fq] = acc;
    __syncthreads();

    const float* shf = (const float*)sh4;
    const float* smf = (const float*)sm4;
#pragma unroll
    for (int o = t; o < 64 * 40; o += 256) {
        int n2 = o / 40, c = o % 40;
        int gn = n0 + n2;
        if (gn < N_NODES) {
            float a = sb[c];
#pragma unroll
            for (int k = 0; k < 16; k++)
                a += shf[n2 * 16 + k] * sw[k * 40 + c]
                   + smf[n2 * 16 + k] * sw[640 + k * 40 + c];
            out[gn * 40 + c] = a;
        }
    }
}

extern "C" void kernel_launch(void* const* d_in, const int* in_sizes, int n_in,
                              void* d_out, int out_size) {
    const float* x   = (const float*)d_in[0];
    const int*   src = (const int*)d_in[1];
    const int*   dst = (const int*)d_in[2];
    const float* wn1 = (const float*)d_in[3];
    const float* ws1 = (const float*)d_in[4];
    const float* b1  = (const float*)d_in[5];
    const float* wn2 = (const float*)d_in[6];
    const float* ws2 = (const float*)d_in[7];
    const float* b2  = (const float*)d_in[8];
    float* out = (float*)d_out;

    void* degp = nullptr;
    cudaGetSymbolAddress(&degp, g_deg);
    cudaMemsetAsync(degp, 0, N_NODES * sizeof(int));

    k_gemm1<<<(N_NODES + 255) / 256, 256>>>(x, wn1, ws1);   // idx 0 (independent)
    k_count<<<(N_EDGES / 4 + 255) / 256, 256>>>(dst);       // idx 1
    k_scan<<<NSCAN_BLOCKS, 512>>>();                        // idx 2
    k_fill<<<(N_EDGES / 4 + 255) / 256, 256>>>(src, dst);   // idx 3 -> profiled
    k_agg1<<<(N_NODES * 4 + 255) / 256, 256>>>(b1);
    k_agg2out<<<(N_NODES + 63) / 64, 256>>>(wn2, ws2, b2, out);
}

// round 6
// speedup vs baseline: 1.4312x; 1.0796x over previous
#include <cuda_runtime.h>
#include <cuda_bf16.h>
#include <cuda_pipeline.h>

#define N_NODES 100000
#define N_EDGES 1600000
#define NFEAT   128
#define NHID    16
#define NCLS    40
#define NSCAN_BLOCKS 196
#define GEMM_BLOCKS ((N_NODES + 255) / 256)          // 391
#define COUNT_BLOCKS ((N_EDGES / 4 + 255) / 256)     // 1563

// -------- scratch (device globals) --------
__device__ float g_p[N_NODES * 32];    // [:,0:16] = x@w_self1, [:,16:32] = x@w_neigh1
__device__ float g_h[N_NODES * 16];    // layer-1 output (post relu)
__device__ int   g_deg[N_NODES];
__device__ int   g_rowptr[N_NODES + 1];
__device__ int   g_rank[N_EDGES];      // edge's rank within its dst group
__device__ int   g_eidx[N_EDGES];      // src ids grouped by dst (CSR)
__device__ unsigned long long g_scanstate[NSCAN_BLOCKS];  // flag(hi32) | value(lo32)

// ===================== fused GEMM1 + degree count =====================
// blocks [0, GEMM_BLOCKS): p = x @ [w_self1 | w_neigh1]  (100000x128)@(128x32)
//   256 threads, 256 rows x 32 cols tile, 4x8 per thread, f32x2 FFMA,
//   K staged in 4 chunks of 32 via cp.async.
// blocks [GEMM_BLOCKS, GEMM_BLOCKS+COUNT_BLOCKS): count in-degrees, record
//   per-edge rank (atomicAdd return), zero scan state.
#define XS_STRIDE 36

__device__ __forceinline__ void ffma2(unsigned long long& acc,
                                      unsigned long long a,
                                      unsigned long long b) {
    asm("fma.rn.f32x2 %0, %1, %2, %0;" : "+l"(acc) : "l"(a), "l"(b));
}

__global__ void __launch_bounds__(256, 2) k_gemm_count(const float* __restrict__ x,
                                                       const float* __restrict__ wn1,
                                                       const float* __restrict__ ws1,
                                                       const int* __restrict__ dst) {
    __shared__ __align__(16) float xs[256 * XS_STRIDE];   // 36 KB
    __shared__ __align__(16) float wt2[4096];             // 16 KB
    int tid = threadIdx.x;

    if (blockIdx.x >= GEMM_BLOCKS) {
        // ---- count branch ----
        int cb = blockIdx.x - GEMM_BLOCKS;
        if (cb == 0 && tid < NSCAN_BLOCKS)
            *(volatile unsigned long long*)&g_scanstate[tid] = 0ULL;
        int e = cb * 256 + tid;
        if (e * 4 < N_EDGES) {
            int4 d = ((const int4*)dst)[e];
            int4 r;
            r.x = atomicAdd(&g_deg[d.x], 1);
            r.y = atomicAdd(&g_deg[d.y], 1);
            r.z = atomicAdd(&g_deg[d.z], 1);
            r.w = atomicAdd(&g_deg[d.w], 1);
            ((int4*)g_rank)[e] = r;
        }
        return;
    }

    // ---- gemm branch ----
    int row0 = blockIdx.x * 256;

    // pack weights: wt2[k4g*128 + c*16 + cg*4 + j] = W[k4g*4+j][cg*8+c]
    for (int i = tid; i < 4096; i += 256) {
        int j   = i & 3;
        int cg  = (i >> 2) & 3;
        int c   = (i >> 4) & 7;
        int k4g = i >> 7;
        int col = cg * 8 + c;
        int k   = k4g * 4 + j;
        wt2[i] = (col < 16) ? ws1[k * 16 + col] : wn1[k * 16 + (col - 16)];
    }

    int cg = tid & 3;        // col group (0..3), 8 cols each
    int rg = tid >> 2;       // row group (0..63), rows rg + q*64

    unsigned long long acc[4][8];
#pragma unroll
    for (int q = 0; q < 4; q++)
#pragma unroll
        for (int c = 0; c < 8; c++) acc[q][c] = 0ULL;

#pragma unroll
    for (int chunk = 0; chunk < 4; chunk++) {
        __syncthreads();
#pragma unroll
        for (int l = 0; l < 8; l++) {
            int f = l * 256 + tid;
            int row = f >> 3, slot = f & 7;
            int gr = row0 + row;
            if (gr >= N_NODES) gr = N_NODES - 1;   // clamp; stores guarded
            __pipeline_memcpy_async(&xs[row * XS_STRIDE + slot * 4],
                                    &x[gr * 128 + chunk * 32 + slot * 4], 16);
        }
        __pipeline_commit();
        __pipeline_wait_prior(0);
        __syncthreads();

#pragma unroll
        for (int k4 = 0; k4 < 8; k4++) {
            int k4g = chunk * 8 + k4;
            const float* wbase = wt2 + k4g * 128 + cg * 4;
            ulonglong2 xv[4];
#pragma unroll
            for (int q = 0; q < 4; q++)
                xv[q] = *(const ulonglong2*)&xs[(rg + q * 64) * XS_STRIDE + k4 * 4];
#pragma unroll
            for (int ch = 0; ch < 2; ch++) {
                ulonglong2 wv[4];
#pragma unroll
                for (int c = 0; c < 4; c++)
                    wv[c] = *(const ulonglong2*)(wbase + (ch * 4 + c) * 16);
#pragma unroll
                for (int q = 0; q < 4; q++)
#pragma unroll
                    for (int c = 0; c < 4; c++)
                        ffma2(acc[q][ch * 4 + c], xv[q].x, wv[c].x);
#pragma unroll
                for (int q = 0; q < 4; q++)
#pragma unroll
                    for (int c = 0; c < 4; c++)
                        ffma2(acc[q][ch * 4 + c], xv[q].y, wv[c].y);
            }
        }
    }

#pragma unroll
    for (int q = 0; q < 4; q++) {
        int gr = row0 + rg + q * 64;
        if (gr < N_NODES) {
            float o[8];
#pragma unroll
            for (int c = 0; c < 8; c++) {
                float2 a = *(float2*)&acc[q][c];
                o[c] = a.x + a.y;
            }
            *(float4*)(&g_p[gr * 32 + cg * 8])     = make_float4(o[0], o[1], o[2], o[3]);
            *(float4*)(&g_p[gr * 32 + cg * 8 + 4]) = make_float4(o[4], o[5], o[6], o[7]);
        }
    }
}

__device__ __forceinline__ int warp_sum(int v) {
#pragma unroll
    for (int o = 16; o; o >>= 1) v += __shfl_xor_sync(0xffffffffu, v, o);
    return v;
}

// -------- single-pass exclusive scan over g_deg (decoupled lookback) --------
__global__ void __launch_bounds__(512) k_scan() {
    __shared__ int s[512];
    __shared__ int s_prev;
    int b = blockIdx.x, t = threadIdx.x;
    int i = b * 512 + t;
    int v = (i < N_NODES) ? g_deg[i] : 0;
    s[t] = v;
    __syncthreads();
#pragma unroll
    for (int off = 1; off < 512; off <<= 1) {
        int tv = (t >= off) ? s[t - off] : 0;
        __syncthreads();
        s[t] += tv;
        __syncthreads();
    }
    int incl = s[t];
    int blocksum = s[511];

    if (t == 0) {
        unsigned long long pkg = ((b == 0) ? (2ULL << 32) : (1ULL << 32))
                               | (unsigned int)blocksum;
        *(volatile unsigned long long*)&g_scanstate[b] = pkg;
    }

    if (t < 32) {
        int prefix = 0;
        int look = b - 1;
        while (look >= 0) {
            int idx = look - t;
            unsigned long long st = (idx >= 0)
                ? *(volatile unsigned long long*)&g_scanstate[idx]
                : (2ULL << 32);
            unsigned int flag = (unsigned int)(st >> 32);
            int val = (int)(st & 0xffffffffu);
            unsigned int nr = __ballot_sync(0xffffffffu, flag == 0u);
            unsigned int pm = __ballot_sync(0xffffffffu, flag == 2u);
            int firstP = pm ? (__ffs(pm) - 1) : 32;
            unsigned int below = (firstP < 32) ? ((1u << firstP) - 1u) : 0xffffffffu;
            if (firstP < 32 && (nr & below) == 0u) {
                int c = (t <= firstP) ? val : 0;
                prefix += warp_sum(c);
                break;
            } else if (nr == 0u) {
                prefix += warp_sum(val);
                look -= 32;
            }
        }
        if (t == 0) {
            s_prev = prefix;
            *(volatile unsigned long long*)&g_scanstate[b] =
                (2ULL << 32) | (unsigned int)(prefix + blocksum);
        }
    }
    __syncthreads();
    int base = s_prev;
    if (i < N_NODES)
        g_rowptr[i] = base + incl - v;
    if (b == NSCAN_BLOCKS - 1 && t == 511)
        g_rowptr[N_NODES] = base + incl;
}

// -------- fill: pos = rowptr[dst] + rank  (no atomics) --------
__global__ void k_fill(const int* __restrict__ src, const int* __restrict__ dst) {
    int e = blockIdx.x * blockDim.x + threadIdx.x;
    if (e * 4 < N_EDGES) {
        int4 s4 = ((const int4*)src)[e];
        int4 d4 = ((const int4*)dst)[e];
        int4 r4 = ((const int4*)g_rank)[e];
        g_eidx[__ldg(&g_rowptr[d4.x]) + r4.x] = s4.x;
        g_eidx[__ldg(&g_rowptr[d4.y]) + r4.y] = s4.y;
        g_eidx[__ldg(&g_rowptr[d4.z]) + r4.z] = s4.z;
        g_eidx[__ldg(&g_rowptr[d4.w]) + r4.w] = s4.w;
    }
}

// -------- layer-1 aggregate + combine + relu --------
__global__ void __launch_bounds__(256) k_agg1(const float* __restrict__ b1) {
    int t = blockIdx.x * blockDim.x + threadIdx.x;
    int n = t >> 2;
    int fq = t & 3;
    if (n >= N_NODES) return;
    int beg = g_rowptr[n];
    int end = g_rowptr[n + 1];
    float4 acc = make_float4(0.f, 0.f, 0.f, 0.f);
    int i = beg;
    for (; i + 4 <= end; i += 4) {
        int s0 = g_eidx[i], s1 = g_eidx[i + 1], s2 = g_eidx[i + 2], s3 = g_eidx[i + 3];
        float4 v0 = *(const float4*)&g_p[s0 * 32 + 16 + fq * 4];
        float4 v1 = *(const float4*)&g_p[s1 * 32 + 16 + fq * 4];
        float4 v2 = *(const float4*)&g_p[s2 * 32 + 16 + fq * 4];
        float4 v3 = *(const float4*)&g_p[s3 * 32 + 16 + fq * 4];
        acc.x += (v0.x + v1.x) + (v2.x + v3.x);
        acc.y += (v0.y + v1.y) + (v2.y + v3.y);
        acc.z += (v0.z + v1.z) + (v2.z + v3.z);
        acc.w += (v0.w + v1.w) + (v2.w + v3.w);
    }
    for (; i < end; i++) {
        int s = g_eidx[i];
        float4 v = *(const float4*)&g_p[s * 32 + 16 + fq * 4];
        acc.x += v.x; acc.y += v.y; acc.z += v.z; acc.w += v.w;
    }
    float inv = 1.f / fmaxf((float)(end - beg), 1.f);
    float4 self = *(const float4*)&g_p[n * 32 + fq * 4];
    float4 bb = *(const float4*)&b1[fq * 4];
    float4 o;
    o.x = fmaxf(self.x + acc.x * inv + bb.x, 0.f);
    o.y = fmaxf(self.y + acc.y * inv + bb.y, 0.f);
    o.z = fmaxf(self.z + acc.z * inv + bb.z, 0.f);
    o.w = fmaxf(self.w + acc.w * inv + bb.w, 0.f);
    *(float4*)&g_h[n * 16 + fq * 4] = o;
}

// -------- fused layer-2 aggregate + output projection --------
__global__ void __launch_bounds__(256) k_agg2out(const float* __restrict__ wn2,
                                                 const float* __restrict__ ws2,
                                                 const float* __restrict__ b2,
                                                 float* __restrict__ out) {
    __shared__ float sw[2 * 640];
    __shared__ float sb[40];
    __shared__ float4 sh4[64 * 4];
    __shared__ float4 sm4[64 * 4];
    int t = threadIdx.x;
    for (int i = t; i < 640; i += 256) { sw[i] = ws2[i]; sw[640 + i] = wn2[i]; }
    if (t < 40) sb[t] = b2[t];

    int n0 = blockIdx.x * 64;
    int nl = t >> 2, fq = t & 3;
    int n = n0 + nl;
    float4 acc = make_float4(0.f, 0.f, 0.f, 0.f);
    float4 hv = make_float4(0.f, 0.f, 0.f, 0.f);
    if (n < N_NODES) {
        int beg = g_rowptr[n];
        int end = g_rowptr[n + 1];
        int i = beg;
        for (; i + 4 <= end; i += 4) {
            int s0 = g_eidx[i], s1 = g_eidx[i + 1], s2 = g_eidx[i + 2], s3 = g_eidx[i + 3];
            float4 v0 = *(const float4*)&g_h[s0 * 16 + fq * 4];
            float4 v1 = *(const float4*)&g_h[s1 * 16 + fq * 4];
            float4 v2 = *(const float4*)&g_h[s2 * 16 + fq * 4];
            float4 v3 = *(const float4*)&g_h[s3 * 16 + fq * 4];
            acc.x += (v0.x + v1.x) + (v2.x + v3.x);
            acc.y += (v0.y + v1.y) + (v2.y + v3.y);
            acc.z += (v0.z + v1.z) + (v2.z + v3.z);
            acc.w += (v0.w + v1.w) + (v2.w + v3.w);
        }
        for (; i < end; i++) {
            int s = g_eidx[i];
            float4 v = *(const float4*)&g_h[s * 16 + fq * 4];
            acc.x += v.x; acc.y += v.y; acc.z += v.z; acc.w += v.w;
        }
        float inv = 1.f / fmaxf((float)(end - beg), 1.f);
        acc.x *= inv; acc.y *= inv; acc.z *= inv; acc.w *= inv;
        hv = *(const float4*)&g_h[n * 16 + fq * 4];
    }
    sh4[nl * 4 + fq] = hv;
    sm4[nl * 4 + fq] = acc;
    __syncthreads();

    const float* shf = (const float*)sh4;
    const float* smf = (const float*)sm4;
#pragma unroll
    for (int o = t; o < 64 * 40; o += 256) {
        int n2 = o / 40, c = o % 40;
        int gn = n0 + n2;
        if (gn < N_NODES) {
            float a = sb[c];
#pragma unroll
            for (int k = 0; k < 16; k++)
                a += shf[n2 * 16 + k] * sw[k * 40 + c]
                   + smf[n2 * 16 + k] * sw[640 + k * 40 + c];
            out[gn * 40 + c] = a;
        }
    }
}

extern "C" void kernel_launch(void* const* d_in, const int* in_sizes, int n_in,
                              void* d_out, int out_size) {
    const float* x   = (const float*)d_in[0];
    const int*   src = (const int*)d_in[1];
    const int*   dst = (const int*)d_in[2];
    const float* wn1 = (const float*)d_in[3];
    const float* ws1 = (const float*)d_in[4];
    const float* b1  = (const float*)d_in[5];
    const float* wn2 = (const float*)d_in[6];
    const float* ws2 = (const float*)d_in[7];
    const float* b2  = (const float*)d_in[8];
    float* out = (float*)d_out;

    void* degp = nullptr;
    cudaGetSymbolAddress(&degp, g_deg);
    cudaMemsetAsync(degp, 0, N_NODES * sizeof(int));

    k_gemm_count<<<GEMM_BLOCKS + COUNT_BLOCKS, 256>>>(x, wn1, ws1, dst);  // idx 0
    k_scan<<<NSCAN_BLOCKS, 512>>>();                                      // idx 1
    k_fill<<<COUNT_BLOCKS, 256>>>(src, dst);                              // idx 2
    k_agg1<<<(N_NODES * 4 + 255) / 256, 256>>>(b1);                       // idx 3 -> profiled
    k_agg2out<<<(N_NODES + 63) / 64, 256>>>(wn2, ws2, b2, out);           // idx 4
}